// round 6
// baseline (speedup 1.0000x reference)
#include <cuda_runtime.h>
#include <cuda_bf16.h>
#include <cstdint>

#define DHEAD 128

// Scratch (no runtime allocation allowed)
__device__ __nv_bfloat16 g_Abf[8192 * DHEAD];
__device__ __nv_bfloat16 g_Bbf[16384 * DHEAD];
__device__ float g_xsq[8192];
__device__ float g_gsq[16384];

__device__ __forceinline__ uint32_t smem_u32(const void* p) {
    uint32_t a;
    asm("{ .reg .u64 t; cvta.to.shared.u64 t, %1; cvt.u32.u64 %0, t; }" : "=r"(a) : "l"(p));
    return a;
}

// ---------------- Kernel 1: fp32 -> bf16 + row norms ----------------
__global__ void __launch_bounds__(256) convert_norm_kernel(
    const float* __restrict__ X, const float* __restrict__ G, int n_img, int n_gts)
{
    int gw = (blockIdx.x * blockDim.x + threadIdx.x) >> 5;
    int lane = threadIdx.x & 31;
    if (gw >= n_img + n_gts) return;
    const float4* src;
    uint2* dst;
    float* nrm;
    if (gw < n_img) {
        src = (const float4*)(X + (size_t)gw * DHEAD);
        dst = (uint2*)(g_Abf + (size_t)gw * DHEAD);
        nrm = g_xsq + gw;
    } else {
        int r = gw - n_img;
        src = (const float4*)(G + (size_t)r * DHEAD);
        dst = (uint2*)(g_Bbf + (size_t)r * DHEAD);
        nrm = g_gsq + r;
    }
    float4 v = src[lane];
    float s = v.x * v.x + v.y * v.y + v.z * v.z + v.w * v.w;
    #pragma unroll
    for (int o = 16; o > 0; o >>= 1) s += __shfl_xor_sync(0xFFFFFFFFu, s, o);
    __nv_bfloat162 p0 = __float22bfloat162_rn(make_float2(v.x, v.y));
    __nv_bfloat162 p1 = __float22bfloat162_rn(make_float2(v.z, v.w));
    uint2 o2;
    o2.x = *reinterpret_cast<uint32_t*>(&p0);
    o2.y = *reinterpret_cast<uint32_t*>(&p1);
    dst[lane] = o2;
    if (lane == 0) *nrm = s;
}

// ---------------- Kernel 2: HMMA GEMM + fused L2 epilogue ----------------
// Per CTA: 128x128 output tile, K=128 fully resident in SMEM.
// Input SMEM: row-major [128][128] bf16 (256B rows), 16B chunks XOR-swizzled
// within the row: chunk' = chunk ^ (row & 7)  -> conflict-free STS + ldmatrix.
// Warp layout: 8 warps as 2 (M) x 4 (N); each warp owns 64x32.
// Epilogue: butterfly shfl (lane^1) assembles float4s; shuffle index is the
// SAME logical block on both lanes of a pair (bug fixed from R5); store is
// predicated so each lane emits 2x STG.128 per (mi,h). Full 128B lines.

static constexpr int SMEM_BYTES = 65536;   // 32 KB A + 32 KB B

__device__ __forceinline__ void ldmatrix_x4(uint32_t* r, uint32_t addr) {
    asm volatile("ldmatrix.sync.aligned.m8n8.x4.shared.b16 {%0,%1,%2,%3}, [%4];"
                 : "=r"(r[0]), "=r"(r[1]), "=r"(r[2]), "=r"(r[3]) : "r"(addr));
}
__device__ __forceinline__ void mma_16816(float* d, const uint32_t* a, const uint32_t* b) {
    asm volatile(
        "mma.sync.aligned.m16n8k16.row.col.f32.bf16.bf16.f32 "
        "{%0,%1,%2,%3}, {%4,%5,%6,%7}, {%8,%9}, {%0,%1,%2,%3};"
        : "+f"(d[0]), "+f"(d[1]), "+f"(d[2]), "+f"(d[3])
        : "r"(a[0]), "r"(a[1]), "r"(a[2]), "r"(a[3]), "r"(b[0]), "r"(b[1]));
}

__global__ void __launch_bounds__(256, 2) l2_mma_kernel(float* __restrict__ out, int n_gts_total)
{
    extern __shared__ char smem[];
    char* sA = smem;
    char* sB = smem + 32768;
    uint32_t sAu = smem_u32(sA);
    uint32_t sBu = smem_u32(sB);

    int tid = threadIdx.x, wid = tid >> 5, lane = tid & 31;
    int ntile = blockIdx.x, mtile = blockIdx.y;

    // ---- Load A/B tiles (each 2048 16B-chunks) into swizzled SMEM ----
    const uint4* Ag = (const uint4*)(g_Abf + (size_t)mtile * 128 * DHEAD);
    const uint4* Bg = (const uint4*)(g_Bbf + (size_t)ntile * 128 * DHEAD);
    #pragma unroll
    for (int k = 0; k < 8; ++k) {
        int i = tid + k * 256;       // chunk index 0..2047
        int r = i >> 4;              // row 0..127
        int c16 = i & 15;            // 16B chunk within row
        uint32_t off = (uint32_t)r * 256u + ((uint32_t)(c16 ^ (r & 7)) << 4);
        *(uint4*)(sA + off) = Ag[i];
        *(uint4*)(sB + off) = Bg[i];
    }
    __syncthreads();

    int wr = wid >> 2;   // 0..1  (M block of 64)
    int wc = wid & 3;    // 0..3  (N block of 32)

    float d[4][4][4];
    #pragma unroll
    for (int mi = 0; mi < 4; ++mi)
        #pragma unroll
        for (int ni = 0; ni < 4; ++ni)
            #pragma unroll
            for (int j = 0; j < 4; ++j) d[mi][ni][j] = 0.0f;

    #pragma unroll
    for (int ks = 0; ks < 8; ++ks) {
        uint32_t a[4][4], b[4][2];
        #pragma unroll
        for (int mi = 0; mi < 4; ++mi) {
            int r = wr * 64 + mi * 16 + (lane & 15);
            int kc = ks * 2 + (lane >> 4);
            uint32_t addr = sAu + (uint32_t)r * 256u + ((uint32_t)(kc ^ (r & 7)) << 4);
            ldmatrix_x4(a[mi], addr);
        }
        // B: x4 ldmatrix covering two n8-fragments at once
        #pragma unroll
        for (int np = 0; np < 2; ++np) {
            int g = lane >> 3;                       // matrix group 0..3
            int r = wc * 32 + (np * 2 + (g >> 1)) * 8 + (lane & 7);
            int kc = ks * 2 + (g & 1);
            uint32_t addr = sBu + (uint32_t)r * 256u + ((uint32_t)(kc ^ (r & 7)) << 4);
            uint32_t q[4];
            ldmatrix_x4(q, addr);
            b[np * 2 + 0][0] = q[0]; b[np * 2 + 0][1] = q[1];
            b[np * 2 + 1][0] = q[2]; b[np * 2 + 1][1] = q[3];
        }
        #pragma unroll
        for (int mi = 0; mi < 4; ++mi)
            #pragma unroll
            for (int ni = 0; ni < 4; ++ni)
                mma_16816(d[mi][ni], a[mi], b[ni]);
    }

    // ---- Fused epilogue: -sqrt(max(xsq + gsq - 2*xg, 0)) + bfly float4 ----
    // Fragment layout: thread holds C[row=lane>>2 (+8)][col=8*ni+2q, +1], q=lane&3.
    int row0 = mtile * 128 + wr * 64 + (lane >> 2);
    int col0 = ntile * 128 + wc * 32 + (lane & 3) * 2;   // for gsq loads
    int q = lane & 3;

    float xs[4][2];
    #pragma unroll
    for (int mi = 0; mi < 4; ++mi) {
        xs[mi][0] = g_xsq[row0 + mi * 16];
        xs[mi][1] = g_xsq[row0 + mi * 16 + 8];
    }
    float gs[4][2];
    #pragma unroll
    for (int ni = 0; ni < 4; ++ni) {
        float2 g2 = *(const float2*)(g_gsq + col0 + ni * 8);
        gs[ni][0] = g2.x;
        gs[ni][1] = g2.y;
    }

    // Pair (q, q^1): assembles float4 covering cols 8a + 4*(q>>1) .. +3.
    // Even lane of pair stores blocks a in {0,1}; odd lane stores {2,3}.
    int colbase = ntile * 128 + wc * 32 + 4 * (q >> 1);
    int qodd = q & 1;

    #pragma unroll
    for (int mi = 0; mi < 4; ++mi) {
        #pragma unroll
        for (int h = 0; h < 2; ++h) {
            float xv = xs[mi][h];
            float2 v[4];
            #pragma unroll
            for (int ni = 0; ni < 4; ++ni) {
                float a0 = d[mi][ni][h * 2 + 0];
                float a1 = d[mi][ni][h * 2 + 1];
                float d20 = fmaxf(fmaf(-2.0f, a0, xv + gs[ni][0]), 0.0f);
                float d21 = fmaxf(fmaf(-2.0f, a1, xv + gs[ni][1]), 0.0f);
                float r0, r1;
                asm("sqrt.approx.f32 %0, %1;" : "=f"(r0) : "f"(d20));
                asm("sqrt.approx.f32 %0, %1;" : "=f"(r1) : "f"(d21));
                v[ni].x = -r0;
                v[ni].y = -r1;
            }
            int grow = row0 + mi * 16 + h * 8;
            float* op = out + (size_t)grow * (size_t)n_gts_total + (size_t)colbase;
            #pragma unroll
            for (int a = 0; a < 4; ++a) {
                // uniform shuffle index: both lanes of a pair exchange v[a]
                float px = __shfl_xor_sync(0xFFFFFFFFu, v[a].x, 1);
                float py = __shfl_xor_sync(0xFFFFFFFFu, v[a].y, 1);
                if ((a >> 1) == qodd) {
                    float4 o;
                    if (qodd) { o.x = px; o.y = py; o.z = v[a].x; o.w = v[a].y; }
                    else      { o.x = v[a].x; o.y = v[a].y; o.z = px; o.w = py; }
                    *(float4*)(op + 8 * a) = o;
                }
            }
        }
    }
}

// ---------------- Launch ----------------
extern "C" void kernel_launch(void* const* d_in, const int* in_sizes, int n_in,
                              void* d_out, int out_size)
{
    const float* X = (const float*)d_in[0];   // image_features [8192,128]
    const float* G = (const float*)d_in[1];   // gts            [16384,128]
    float* out = (float*)d_out;               // [8192,16384] fp32

    int n_img = in_sizes[0] / DHEAD;
    int n_gts = in_sizes[1] / DHEAD;

    int total_warps = n_img + n_gts;
    int cblocks = (total_warps * 32 + 255) / 256;
    convert_norm_kernel<<<cblocks, 256>>>(X, G, n_img, n_gts);

    cudaFuncSetAttribute(l2_mma_kernel, cudaFuncAttributeMaxDynamicSharedMemorySize, SMEM_BYTES);
    dim3 grid(n_gts / 128, n_img / 128);
    l2_mma_kernel<<<grid, 256, SMEM_BYTES>>>(out, n_gts);
}

// round 7
// speedup vs baseline: 1.5583x; 1.5583x over previous
#include <cuda_runtime.h>
#include <cuda_bf16.h>
#include <cstdint>

#define DHEAD 128

// Scratch (no runtime allocation allowed)
__device__ __nv_bfloat16 g_Abf[8192 * DHEAD];
__device__ __nv_bfloat16 g_Bbf[16384 * DHEAD];
__device__ float g_xsq[8192];
__device__ float g_gsq[16384];

__device__ __forceinline__ uint32_t smem_u32(const void* p) {
    uint32_t a;
    asm("{ .reg .u64 t; cvta.to.shared.u64 t, %1; cvt.u32.u64 %0, t; }" : "=r"(a) : "l"(p));
    return a;
}

// ---------------- Kernel 1: fp32 -> bf16 + row norms ----------------
__global__ void __launch_bounds__(256) convert_norm_kernel(
    const float* __restrict__ X, const float* __restrict__ G, int n_img, int n_gts)
{
    int gw = (blockIdx.x * blockDim.x + threadIdx.x) >> 5;
    int lane = threadIdx.x & 31;
    if (gw >= n_img + n_gts) return;
    const float4* src;
    uint2* dst;
    float* nrm;
    if (gw < n_img) {
        src = (const float4*)(X + (size_t)gw * DHEAD);
        dst = (uint2*)(g_Abf + (size_t)gw * DHEAD);
        nrm = g_xsq + gw;
    } else {
        int r = gw - n_img;
        src = (const float4*)(G + (size_t)r * DHEAD);
        dst = (uint2*)(g_Bbf + (size_t)r * DHEAD);
        nrm = g_gsq + r;
    }
    float4 v = src[lane];
    float s = v.x * v.x + v.y * v.y + v.z * v.z + v.w * v.w;
    #pragma unroll
    for (int o = 16; o > 0; o >>= 1) s += __shfl_xor_sync(0xFFFFFFFFu, s, o);
    __nv_bfloat162 p0 = __float22bfloat162_rn(make_float2(v.x, v.y));
    __nv_bfloat162 p1 = __float22bfloat162_rn(make_float2(v.z, v.w));
    uint2 o2;
    o2.x = *reinterpret_cast<uint32_t*>(&p0);
    o2.y = *reinterpret_cast<uint32_t*>(&p1);
    dst[lane] = o2;
    if (lane == 0) *nrm = s;
}

// ---------------- Kernel 2: HMMA GEMM + fused L2 epilogue ----------------
// Per CTA: 128x128 output tile, K=128 fully resident in SMEM.
// Input SMEM: row-major [128][128] bf16 (256B rows), 16B chunks XOR-swizzled
// within the row: chunk' = chunk ^ (row & 7)  -> conflict-free STS + ldmatrix.
//
// B ROW PERMUTATION: within each 32-row group, B rows are stored permuted by
// the involution f=8u+2v+e <-> j=8v+2u+e. Fragment position f of the C tile
// then corresponds to output column 8q+2ni+e, i.e. each thread's 4 ni-blocks
// hold 8 CONSECUTIVE output columns -> epilogue stores two STG.128 per
// (mi,h) with no shuffles/barriers (64B per row per inst instead of 32B).
//
// Warp layout: 8 warps as 2 (M) x 4 (N); each warp owns 64x32.
// Input tiles loaded with cp.async.cg (16B) straight into swizzled SMEM.

static constexpr int SMEM_BYTES = 65536;   // 32 KB A + 32 KB B

__device__ __forceinline__ void ldmatrix_x4(uint32_t* r, uint32_t addr) {
    asm volatile("ldmatrix.sync.aligned.m8n8.x4.shared.b16 {%0,%1,%2,%3}, [%4];"
                 : "=r"(r[0]), "=r"(r[1]), "=r"(r[2]), "=r"(r[3]) : "r"(addr));
}
__device__ __forceinline__ void mma_16816(float* d, const uint32_t* a, const uint32_t* b) {
    asm volatile(
        "mma.sync.aligned.m16n8k16.row.col.f32.bf16.bf16.f32 "
        "{%0,%1,%2,%3}, {%4,%5,%6,%7}, {%8,%9}, {%0,%1,%2,%3};"
        : "+f"(d[0]), "+f"(d[1]), "+f"(d[2]), "+f"(d[3])
        : "r"(a[0]), "r"(a[1]), "r"(a[2]), "r"(a[3]), "r"(b[0]), "r"(b[1]));
}
__device__ __forceinline__ void cp_async16(uint32_t smem_addr, const void* gptr) {
    asm volatile("cp.async.cg.shared.global [%0], [%1], 16;"
                 :: "r"(smem_addr), "l"(gptr) : "memory");
}

__global__ void __launch_bounds__(256, 2) l2_mma_kernel(float* __restrict__ out, int n_gts_total)
{
    extern __shared__ char smem[];
    uint32_t sAu = smem_u32(smem);
    uint32_t sBu = sAu + 32768;

    int tid = threadIdx.x, wid = tid >> 5, lane = tid & 31;
    int ntile = blockIdx.x, mtile = blockIdx.y;

    // ---- cp.async A/B tiles (each 2048 16B-chunks) into swizzled SMEM ----
    const char* Ag = (const char*)(g_Abf + (size_t)mtile * 128 * DHEAD);
    const char* Bg = (const char*)(g_Bbf + (size_t)ntile * 128 * DHEAD);
    #pragma unroll
    for (int k = 0; k < 8; ++k) {
        int i = tid + k * 256;       // chunk index 0..2047
        int r = i >> 4;              // source row 0..127
        int c16 = i & 15;            // 16B chunk within row
        // A: identity row
        uint32_t offA = (uint32_t)r * 256u + ((uint32_t)(c16 ^ (r & 7)) << 4);
        cp_async16(sAu + offA, Ag + i * 16);
        // B: permuted destination row rp = (r&96) | ((r&6)<<2) | ((r>>2)&6) | (r&1)
        int rp = (r & 96) | ((r & 6) << 2) | ((r >> 2) & 6) | (r & 1);
        uint32_t offB = (uint32_t)rp * 256u + ((uint32_t)(c16 ^ (rp & 7)) << 4);
        cp_async16(sBu + offB, Bg + i * 16);
    }
    asm volatile("cp.async.commit_group;" ::: "memory");
    asm volatile("cp.async.wait_group 0;" ::: "memory");
    __syncthreads();

    int wr = wid >> 2;   // 0..1  (M block of 64)
    int wc = wid & 3;    // 0..3  (N block of 32)

    float d[4][4][4];
    #pragma unroll
    for (int mi = 0; mi < 4; ++mi)
        #pragma unroll
        for (int ni = 0; ni < 4; ++ni)
            #pragma unroll
            for (int j = 0; j < 4; ++j) d[mi][ni][j] = 0.0f;

    #pragma unroll
    for (int ks = 0; ks < 8; ++ks) {
        uint32_t a[4][4], b[4][2];
        #pragma unroll
        for (int mi = 0; mi < 4; ++mi) {
            int r = wr * 64 + mi * 16 + (lane & 15);
            int kc = ks * 2 + (lane >> 4);
            uint32_t addr = sAu + (uint32_t)r * 256u + ((uint32_t)(kc ^ (r & 7)) << 4);
            ldmatrix_x4(a[mi], addr);
        }
        // B: x4 ldmatrix covering two n8-fragments at once
        #pragma unroll
        for (int np = 0; np < 2; ++np) {
            int g = lane >> 3;                       // matrix group 0..3
            int r = wc * 32 + (np * 2 + (g >> 1)) * 8 + (lane & 7);
            int kc = ks * 2 + (g & 1);
            uint32_t addr = sBu + (uint32_t)r * 256u + ((uint32_t)(kc ^ (r & 7)) << 4);
            uint32_t q[4];
            ldmatrix_x4(q, addr);
            b[np * 2 + 0][0] = q[0]; b[np * 2 + 0][1] = q[1];
            b[np * 2 + 1][0] = q[2]; b[np * 2 + 1][1] = q[3];
        }
        #pragma unroll
        for (int mi = 0; mi < 4; ++mi)
            #pragma unroll
            for (int ni = 0; ni < 4; ++ni)
                mma_16816(d[mi][ni], a[mi], b[ni]);
    }

    // ---- Fused epilogue: -sqrt(max(xsq + gsq - 2*xg, 0)) ----
    // With permuted B: thread (q=lane&3) fragment (ni, e) = output col 8q+2ni+e
    // -> each thread owns 8 consecutive columns. Rows unchanged.
    int q = lane & 3;
    int row0 = mtile * 128 + wr * 64 + (lane >> 2);
    int colbase = ntile * 128 + wc * 32 + 8 * q;

    float xs[4][2];
    #pragma unroll
    for (int mi = 0; mi < 4; ++mi) {
        xs[mi][0] = g_xsq[row0 + mi * 16];
        xs[mi][1] = g_xsq[row0 + mi * 16 + 8];
    }
    float gs[4][2];
    #pragma unroll
    for (int ni = 0; ni < 4; ++ni) {
        float2 g2 = *(const float2*)(g_gsq + colbase + 2 * ni);
        gs[ni][0] = g2.x;
        gs[ni][1] = g2.y;
    }

    #pragma unroll
    for (int mi = 0; mi < 4; ++mi) {
        #pragma unroll
        for (int h = 0; h < 2; ++h) {
            float xv = xs[mi][h];
            float v[8];
            #pragma unroll
            for (int ni = 0; ni < 4; ++ni) {
                float a0 = d[mi][ni][h * 2 + 0];
                float a1 = d[mi][ni][h * 2 + 1];
                float d20 = fmaxf(fmaf(-2.0f, a0, xv + gs[ni][0]), 0.0f);
                float d21 = fmaxf(fmaf(-2.0f, a1, xv + gs[ni][1]), 0.0f);
                float r0, r1;
                asm("sqrt.approx.f32 %0, %1;" : "=f"(r0) : "f"(d20));
                asm("sqrt.approx.f32 %0, %1;" : "=f"(r1) : "f"(d21));
                v[2 * ni]     = -r0;
                v[2 * ni + 1] = -r1;
            }
            int grow = row0 + mi * 16 + h * 8;
            float* op = out + (size_t)grow * (size_t)n_gts_total + (size_t)colbase;
            float4 o0 = make_float4(v[0], v[1], v[2], v[3]);
            float4 o1 = make_float4(v[4], v[5], v[6], v[7]);
            *(float4*)(op)     = o0;
            *(float4*)(op + 4) = o1;
        }
    }
}

// ---------------- Launch ----------------
extern "C" void kernel_launch(void* const* d_in, const int* in_sizes, int n_in,
                              void* d_out, int out_size)
{
    const float* X = (const float*)d_in[0];   // image_features [8192,128]
    const float* G = (const float*)d_in[1];   // gts            [16384,128]
    float* out = (float*)d_out;               // [8192,16384] fp32

    int n_img = in_sizes[0] / DHEAD;
    int n_gts = in_sizes[1] / DHEAD;

    int total_warps = n_img + n_gts;
    int cblocks = (total_warps * 32 + 255) / 256;
    convert_norm_kernel<<<cblocks, 256>>>(X, G, n_img, n_gts);

    cudaFuncSetAttribute(l2_mma_kernel, cudaFuncAttributeMaxDynamicSharedMemorySize, SMEM_BYTES);
    dim3 grid(n_gts / 128, n_img / 128);
    l2_mma_kernel<<<grid, 256, SMEM_BYTES>>>(out, n_gts);
}

// round 9
// speedup vs baseline: 1.7344x; 1.1130x over previous
#include <cuda_runtime.h>
#include <cuda_bf16.h>
#include <cstdint>

#define DHEAD 128

// Scratch (no runtime allocation allowed)
__device__ __nv_bfloat16 g_Abf[8192 * DHEAD];
__device__ __nv_bfloat16 g_Bbf[16384 * DHEAD];
__device__ float g_xsq[8192];
__device__ float g_gsq[16384];

__device__ __forceinline__ uint32_t smem_u32(const void* p) {
    uint32_t a;
    asm("{ .reg .u64 t; cvta.to.shared.u64 t, %1; cvt.u32.u64 %0, t; }" : "=r"(a) : "l"(p));
    return a;
}

// ---------------- Kernel 1: fp32 -> bf16 + row norms ----------------
__global__ void __launch_bounds__(256) convert_norm_kernel(
    const float* __restrict__ X, const float* __restrict__ G, int n_img, int n_gts)
{
    int gw = (blockIdx.x * blockDim.x + threadIdx.x) >> 5;
    int lane = threadIdx.x & 31;
    if (gw >= n_img + n_gts) return;
    const float4* src;
    uint2* dst;
    float* nrm;
    if (gw < n_img) {
        src = (const float4*)(X + (size_t)gw * DHEAD);
        dst = (uint2*)(g_Abf + (size_t)gw * DHEAD);
        nrm = g_xsq + gw;
    } else {
        int r = gw - n_img;
        src = (const float4*)(G + (size_t)r * DHEAD);
        dst = (uint2*)(g_Bbf + (size_t)r * DHEAD);
        nrm = g_gsq + r;
    }
    float4 v = src[lane];
    float s = v.x * v.x + v.y * v.y + v.z * v.z + v.w * v.w;
    #pragma unroll
    for (int o = 16; o > 0; o >>= 1) s += __shfl_xor_sync(0xFFFFFFFFu, s, o);
    __nv_bfloat162 p0 = __float22bfloat162_rn(make_float2(v.x, v.y));
    __nv_bfloat162 p1 = __float22bfloat162_rn(make_float2(v.z, v.w));
    uint2 o2;
    o2.x = *reinterpret_cast<uint32_t*>(&p0);
    o2.y = *reinterpret_cast<uint32_t*>(&p1);
    dst[lane] = o2;
    if (lane == 0) *nrm = s;
}

// ---------------- Kernel 2: pipelined multi-tile HMMA + fused L2 epilogue ---
// Each CTA: one 128-row A tile (resident), walks NT=4 consecutive 128-col B
// tiles with double-buffered cp.async prefetch (load of B(t+1) overlaps MMA +
// epilogue of tile t). SMEM: A 32KB + 2x B 32KB = 96KB -> 2 CTA/SM.
//
// Input SMEM: row-major [128][128] bf16 (256B rows), 16B chunks XOR-swizzled:
// chunk' = chunk ^ (row & 7) -> conflict-free fill + ldmatrix.
// B ROW PERMUTATION (involution f=8u+2v+e <-> 8v+2u+e) at fill time makes each
// thread's 4 ni-fragments hold 8 consecutive output columns -> epilogue is two
// STG.128 per (mi,h), no shuffles, no barriers.
// Warp layout: 8 warps as 2 (M) x 4 (N); each warp owns 64x32 of the tile.

static constexpr int NT = 4;                     // B tiles per CTA
static constexpr int SMEM_BYTES = 98304;         // 32KB A + 2*32KB B

__device__ __forceinline__ void ldmatrix_x4(uint32_t* r, uint32_t addr) {
    asm volatile("ldmatrix.sync.aligned.m8n8.x4.shared.b16 {%0,%1,%2,%3}, [%4];"
                 : "=r"(r[0]), "=r"(r[1]), "=r"(r[2]), "=r"(r[3]) : "r"(addr));
}
__device__ __forceinline__ void mma_16816(float* d, const uint32_t* a, const uint32_t* b) {
    asm volatile(
        "mma.sync.aligned.m16n8k16.row.col.f32.bf16.bf16.f32 "
        "{%0,%1,%2,%3}, {%4,%5,%6,%7}, {%8,%9}, {%0,%1,%2,%3};"
        : "+f"(d[0]), "+f"(d[1]), "+f"(d[2]), "+f"(d[3])
        : "r"(a[0]), "r"(a[1]), "r"(a[2]), "r"(a[3]), "r"(b[0]), "r"(b[1]));
}
__device__ __forceinline__ void cp_async16(uint32_t smem_addr, const void* gptr) {
    asm volatile("cp.async.cg.shared.global [%0], [%1], 16;"
                 :: "r"(smem_addr), "l"(gptr) : "memory");
}

// Fill one 128x128 bf16 B tile into swizzled+permuted SMEM (8 cp.async/thread)
__device__ __forceinline__ void fill_B(uint32_t sBu, const char* Bg, int tid) {
    #pragma unroll
    for (int k = 0; k < 8; ++k) {
        int i = tid + k * 256;       // chunk 0..2047
        int r = i >> 4;
        int c16 = i & 15;
        int rp = (r & 96) | ((r & 6) << 2) | ((r >> 2) & 6) | (r & 1);
        uint32_t off = (uint32_t)rp * 256u + ((uint32_t)(c16 ^ (rp & 7)) << 4);
        cp_async16(sBu + off, Bg + i * 16);
    }
}

__global__ void __launch_bounds__(256, 2) l2_mma_kernel(float* __restrict__ out, int n_gts_total)
{
    extern __shared__ char smem[];
    uint32_t sAu = smem_u32(smem);
    uint32_t sB0 = sAu + 32768;

    int tid = threadIdx.x, wid = tid >> 5, lane = tid & 31;
    int ngrp = blockIdx.x;           // group of NT n-tiles
    int mtile = blockIdx.y;

    // ---- Prologue: A tile + B tile 0 ----
    const char* Ag = (const char*)(g_Abf + (size_t)mtile * 128 * DHEAD);
    const char* Bg0 = (const char*)(g_Bbf + (size_t)(ngrp * NT) * 128 * DHEAD);
    #pragma unroll
    for (int k = 0; k < 8; ++k) {
        int i = tid + k * 256;
        int r = i >> 4;
        int c16 = i & 15;
        uint32_t off = (uint32_t)r * 256u + ((uint32_t)(c16 ^ (r & 7)) << 4);
        cp_async16(sAu + off, Ag + i * 16);
    }
    fill_B(sB0, Bg0, tid);
    asm volatile("cp.async.commit_group;" ::: "memory");
    asm volatile("cp.async.wait_group 0;" ::: "memory");
    __syncthreads();

    int wr = wid >> 2;   // 0..1  (M block of 64)
    int wc = wid & 3;    // 0..3  (N block of 32)
    int q = lane & 3;

    int row0 = mtile * 128 + wr * 64 + (lane >> 2);
    float xs[4][2];
    #pragma unroll
    for (int mi = 0; mi < 4; ++mi) {
        xs[mi][0] = g_xsq[row0 + mi * 16];
        xs[mi][1] = g_xsq[row0 + mi * 16 + 8];
    }

    for (int t = 0; t < NT; ++t) {
        uint32_t sBu = sB0 + (uint32_t)(t & 1) * 32768u;

        // prefetch next B tile into the other buffer
        if (t + 1 < NT) {
            const char* Bgn = (const char*)(g_Bbf + (size_t)(ngrp * NT + t + 1) * 128 * DHEAD);
            fill_B(sB0 + (uint32_t)((t + 1) & 1) * 32768u, Bgn, tid);
            asm volatile("cp.async.commit_group;" ::: "memory");
        }

        float d[4][4][4];
        #pragma unroll
        for (int mi = 0; mi < 4; ++mi)
            #pragma unroll
            for (int ni = 0; ni < 4; ++ni)
                #pragma unroll
                for (int j = 0; j < 4; ++j) d[mi][ni][j] = 0.0f;

        #pragma unroll
        for (int ks = 0; ks < 8; ++ks) {
            uint32_t a[4][4], b[4][2];
            #pragma unroll
            for (int mi = 0; mi < 4; ++mi) {
                int r = wr * 64 + mi * 16 + (lane & 15);
                int kc = ks * 2 + (lane >> 4);
                uint32_t addr = sAu + (uint32_t)r * 256u + ((uint32_t)(kc ^ (r & 7)) << 4);
                ldmatrix_x4(a[mi], addr);
            }
            #pragma unroll
            for (int np = 0; np < 2; ++np) {
                int g = lane >> 3;
                int r = wc * 32 + (np * 2 + (g >> 1)) * 8 + (lane & 7);
                int kc = ks * 2 + (g & 1);
                uint32_t addr = sBu + (uint32_t)r * 256u + ((uint32_t)(kc ^ (r & 7)) << 4);
                uint32_t qq[4];
                ldmatrix_x4(qq, addr);
                b[np * 2 + 0][0] = qq[0]; b[np * 2 + 0][1] = qq[1];
                b[np * 2 + 1][0] = qq[2]; b[np * 2 + 1][1] = qq[3];
            }
            #pragma unroll
            for (int mi = 0; mi < 4; ++mi)
                #pragma unroll
                for (int ni = 0; ni < 4; ++ni)
                    mma_16816(d[mi][ni], a[mi], b[ni]);
        }

        // ---- Epilogue for tile t: -sqrt(max(xsq + gsq - 2*xg, 0)) ----
        int colbase = (ngrp * NT + t) * 128 + wc * 32 + 8 * q;
        float gs[4][2];
        #pragma unroll
        for (int ni = 0; ni < 4; ++ni) {
            float2 g2 = *(const float2*)(g_gsq + colbase + 2 * ni);
            gs[ni][0] = g2.x;
            gs[ni][1] = g2.y;
        }

        #pragma unroll
        for (int mi = 0; mi < 4; ++mi) {
            #pragma unroll
            for (int h = 0; h < 2; ++h) {
                float xv = xs[mi][h];
                float v[8];
                #pragma unroll
                for (int ni = 0; ni < 4; ++ni) {
                    float a0 = d[mi][ni][h * 2 + 0];
                    float a1 = d[mi][ni][h * 2 + 1];
                    float d20 = fmaxf(fmaf(-2.0f, a0, xv + gs[ni][0]), 0.0f);
                    float d21 = fmaxf(fmaf(-2.0f, a1, xv + gs[ni][1]), 0.0f);
                    float r0, r1;
                    asm("sqrt.approx.f32 %0, %1;" : "=f"(r0) : "f"(d20));
                    asm("sqrt.approx.f32 %0, %1;" : "=f"(r1) : "f"(d21));
                    v[2 * ni]     = -r0;
                    v[2 * ni + 1] = -r1;
                }
                int grow = row0 + mi * 16 + h * 8;
                float* op = out + (size_t)grow * (size_t)n_gts_total + (size_t)colbase;
                *(float4*)(op)     = make_float4(v[0], v[1], v[2], v[3]);
                *(float4*)(op + 4) = make_float4(v[4], v[5], v[6], v[7]);
            }
        }

        if (t + 1 < NT) {
            asm volatile("cp.async.wait_group 0;" ::: "memory");
            __syncthreads();
        }
    }
}

// ---------------- Launch ----------------
extern "C" void kernel_launch(void* const* d_in, const int* in_sizes, int n_in,
                              void* d_out, int out_size)
{
    const float* X = (const float*)d_in[0];   // image_features [8192,128]
    const float* G = (const float*)d_in[1];   // gts            [16384,128]
    float* out = (float*)d_out;               // [8192,16384] fp32

    int n_img = in_sizes[0] / DHEAD;
    int n_gts = in_sizes[1] / DHEAD;

    int total_warps = n_img + n_gts;
    int cblocks = (total_warps * 32 + 255) / 256;
    convert_norm_kernel<<<cblocks, 256>>>(X, G, n_img, n_gts);

    cudaFuncSetAttribute(l2_mma_kernel, cudaFuncAttributeMaxDynamicSharedMemorySize, SMEM_BYTES);
    dim3 grid(n_gts / (128 * NT), n_img / 128);
    l2_mma_kernel<<<grid, 256, SMEM_BYTES>>>(out, n_gts);
}